// round 14
// baseline (speedup 1.0000x reference)
#include <cuda_runtime.h>
#include <math.h>
#include <stdint.h>
#include <stdio.h>

// Problem constants
#define BATCH 4
#define CDIM  1024
#define TDIM  1024
#define HEADS 16
#define DHEAD 64
#define DROPE 32

// ---------------------------------------------------------------------------
// Scratch (device globals; no allocation anywhere)
// ---------------------------------------------------------------------------
__device__ float g_proj[(size_t)BATCH * CDIM * TDIM];      // q projection [B,C,T]
__device__ float g_kv  [(size_t)BATCH * 2 * CDIM * TDIM];  // kv projection [B,2C,T]
__device__ float g_q   [(size_t)BATCH * CDIM * TDIM];      // Q [B,H,T,DH]
__device__ float g_k   [(size_t)BATCH * CDIM * TDIM];      // K [B,H,T,DH]
__device__ float g_v   [(size_t)BATCH * CDIM * TDIM];      // V [B,H,T,DH]
__device__ float g_attn[(size_t)BATCH * CDIM * TDIM];      // attn output [B,C,T]

// ---------------------------------------------------------------------------
// Naive GEMM, einsum('oc,bct->bot') transcribed directly.
// One thread = one (b, o, t) output element. grid = (T/256, M, B).
// ---------------------------------------------------------------------------
__global__ __launch_bounds__(256)
void ngemm(const float* __restrict__ W, const float* __restrict__ Xin,
           const float* __restrict__ bias, float* __restrict__ Out,
           long xStride, long oStride)
{
    int t = blockIdx.x * 256 + threadIdx.x;   // 0..T-1
    int o = blockIdx.y;                        // 0..M-1
    int b = blockIdx.z;

    const float* Xb = Xin + (long)b * xStride;       // [C][T]
    const float* Wr = W + (long)o * CDIM;            // row o of W [M][C]

    float s = 0.f;
    for (int cc = 0; cc < CDIM; cc++)
        s = fmaf(Wr[cc], Xb[(long)cc * TDIM + t], s);

    Out[(long)b * oStride + (long)o * TDIM + t] = s + bias[o];
}

// ---------------------------------------------------------------------------
// Build Q, K, V in [B,H,T,DH] from the projection buffers, applying RoPE to
// the first 32 dims of Q and K. Direct per-element transcription:
//   theta_j = 10000^(-2j/32), j = d mod 16
//   d <  16 : out = x_d cos(t*theta) - x_{d+16} sin(t*theta)
//   16<=d<32: out = x_d cos(t*theta) + x_{d-16} sin(t*theta)
//   d >= 32 : passthrough
// Q additionally folds the 1/sqrt(DH) = 0.125 score scale.
// Thread id -> (b, h, d, t) with t fastest.
// ---------------------------------------------------------------------------
__global__ __launch_bounds__(256)
void build_qkv(const float* __restrict__ qproj,   // [B][C][T]
               const float* __restrict__ kvproj,  // [B][2C][T]
               float* __restrict__ Qd, float* __restrict__ Kd,
               float* __restrict__ Vd)
{
    long gid = (long)blockIdx.x * blockDim.x + threadIdx.x;  // < B*H*DH*T = 4M
    int  t  = (int)(gid & (TDIM - 1));
    long r  = gid >> 10;            // b*H*DH + h*DH + d
    int  d  = (int)(r & (DHEAD - 1));
    long bh = r >> 6;               // b*H + h
    int  h  = (int)(bh & (HEADS - 1));
    int  b  = (int)(bh >> 4);

    float qv = qproj [((long)b * CDIM     + h * DHEAD + d) * TDIM + t];
    float kv = kvproj[((long)b * 2 * CDIM + h * DHEAD + d) * TDIM + t];
    float vv = kvproj[((long)b * 2 * CDIM + CDIM + h * DHEAD + d) * TDIM + t];

    if (d < DROPE) {
        int   j     = (d < 16) ? d : d - 16;
        float theta = powf(10000.f, -(float)(2 * j) / 32.f);
        float ang   = theta * (float)t;
        float cs    = cosf(ang);
        float sn    = sinf(ang);
        int   pd    = (d < 16) ? d + 16 : d - 16;
        float sgn   = (d < 16) ? -1.f : 1.f;
        float qp = qproj [((long)b * CDIM     + h * DHEAD + pd) * TDIM + t];
        float kp = kvproj[((long)b * 2 * CDIM + h * DHEAD + pd) * TDIM + t];
        qv = qv * cs + sgn * qp * sn;
        kv = kv * cs + sgn * kp * sn;
    }

    long dst = (((long)(b * HEADS + h) * TDIM) + t) * DHEAD + d;
    Qd[dst] = qv * 0.125f;   // fold score scale into Q
    Kd[dst] = kv;
    Vd[dst] = vv;
}

// ---------------------------------------------------------------------------
// Naive attention: one warp per (b, h, q) row. Three passes over all keys:
//   1) m = max_k s(k)     2) l = sum_k exp(s-m)     3) out = sum_k exp(s-m)/l V
// Each lane owns dims {2*lane, 2*lane+1}; full-warp shuffle sum per key.
// Output written directly in [B, C, T] layout (out[b, h*64+d, q]).
// ---------------------------------------------------------------------------
__global__ __launch_bounds__(128)
void attn_naive(const float* __restrict__ Qd, const float* __restrict__ Kd,
                const float* __restrict__ Vd, float* __restrict__ Od)
{
    int warp = threadIdx.x >> 5;        // 0..3
    int lane = threadIdx.x & 31;
    int qrow = blockIdx.x * 4 + warp;   // 0..T-1
    int h = blockIdx.y;
    int b = blockIdx.z;

    const float* Qr  = Qd + (((long)(b * HEADS + h) * TDIM) + qrow) * DHEAD;
    const float* Kbh = Kd + ((long)(b * HEADS + h) * TDIM) * DHEAD;
    const float* Vbh = Vd + ((long)(b * HEADS + h) * TDIM) * DHEAD;

    float2 qv = *(const float2*)(Qr + lane * 2);

    // pass 1: row max
    float m = -INFINITY;
    for (int k = 0; k < TDIM; k++) {
        float2 kv2 = *(const float2*)(Kbh + (long)k * DHEAD + lane * 2);
        float p = qv.x * kv2.x + qv.y * kv2.y;
        #pragma unroll
        for (int o = 16; o >= 1; o >>= 1) p += __shfl_xor_sync(0xffffffffu, p, o);
        m = fmaxf(m, p);
    }

    // pass 2: denominator
    float l = 0.f;
    for (int k = 0; k < TDIM; k++) {
        float2 kv2 = *(const float2*)(Kbh + (long)k * DHEAD + lane * 2);
        float p = qv.x * kv2.x + qv.y * kv2.y;
        #pragma unroll
        for (int o = 16; o >= 1; o >>= 1) p += __shfl_xor_sync(0xffffffffu, p, o);
        l += expf(p - m);
    }

    // pass 3: weighted V accumulation
    float a0 = 0.f, a1 = 0.f;
    for (int k = 0; k < TDIM; k++) {
        float2 kv2 = *(const float2*)(Kbh + (long)k * DHEAD + lane * 2);
        float p = qv.x * kv2.x + qv.y * kv2.y;
        #pragma unroll
        for (int o = 16; o >= 1; o >>= 1) p += __shfl_xor_sync(0xffffffffu, p, o);
        float w = expf(p - m);
        float2 vv = *(const float2*)(Vbh + (long)k * DHEAD + lane * 2);
        a0 = fmaf(w, vv.x, a0);
        a1 = fmaf(w, vv.y, a1);
    }

    float inv = 1.f / l;
    long base = ((long)b * CDIM + h * DHEAD) * TDIM + qrow;
    Od[base + (long)(lane * 2    ) * TDIM] = a0 * inv;
    Od[base + (long)(lane * 2 + 1) * TDIM] = a1 * inv;
}

// ---------------------------------------------------------------------------
// Host launcher
// ---------------------------------------------------------------------------
extern "C" void kernel_launch(void* const* d_in, const int* in_sizes, int n_in,
                              void* d_out, int out_size)
{
    // Sanity-check input ordering/sizes; print only on mismatch (diagnostic).
    const int exp_sizes[8] = {4194304, 4194304, 1048576, 1024,
                              2097152, 2048, 1048576, 1024};
    bool ok = (n_in == 8);
    if (ok)
        for (int i = 0; i < 8; i++)
            if (in_sizes[i] != exp_sizes[i]) ok = false;
    if (!ok) {
        printf("IN_SIZES_MISMATCH n_in=%d:", n_in);
        for (int i = 0; i < n_in; i++) printf(" %d", in_sizes[i]);
        printf("\n");
    }

    const float* x    = (const float*)d_in[0];
    const float* c    = (const float*)d_in[1];
    const float* q_w  = (const float*)d_in[2];
    const float* q_b  = (const float*)d_in[3];
    const float* kv_w = (const float*)d_in[4];
    const float* kv_b = (const float*)d_in[5];
    const float* o_w  = (const float*)d_in[6];
    const float* o_b  = (const float*)d_in[7];
    float* out = (float*)d_out;

    float *proj, *kv, *qr, *kr, *vr, *attnOut;
    cudaGetSymbolAddress((void**)&proj,    g_proj);
    cudaGetSymbolAddress((void**)&kv,      g_kv);
    cudaGetSymbolAddress((void**)&qr,      g_q);
    cudaGetSymbolAddress((void**)&kr,      g_k);
    cudaGetSymbolAddress((void**)&vr,      g_v);
    cudaGetSymbolAddress((void**)&attnOut, g_attn);

    const long CT  = (long)CDIM * TDIM;     // 1M
    const long C2T = 2 * CT;                // 2M

    // q = q_w @ x + q_b      -> proj [B, C, T]
    ngemm<<<dim3(TDIM / 256, CDIM, BATCH), 256>>>(q_w, x, q_b, proj, CT, CT);

    // kv = kv_w @ c + kv_b   -> kv [B, 2C, T]
    ngemm<<<dim3(TDIM / 256, 2 * CDIM, BATCH), 256>>>(kv_w, c, kv_b, kv, CT, C2T);

    // Q/K/V build + RoPE      -> [B, H, T, DH]
    {
        long total = (long)BATCH * HEADS * DHEAD * TDIM;   // 4M
        build_qkv<<<(unsigned)(total / 256), 256>>>(proj, kv, qr, kr, vr);
    }

    // attention               -> attnOut [B, C, T]
    attn_naive<<<dim3(TDIM / 4, HEADS, BATCH), 128>>>(qr, kr, vr, attnOut);

    // out = o_w @ attn + o_b
    ngemm<<<dim3(TDIM / 256, CDIM, BATCH), 256>>>(o_w, attnOut, o_b, out, CT, CT);
}

// round 16
// speedup vs baseline: 1.9967x; 1.9967x over previous
#include <cuda_runtime.h>
#include <math.h>
#include <stdint.h>
#include <stdio.h>

// Problem constants
#define BATCH 4
#define CDIM  1024
#define TDIM  1024
#define HEADS 16
#define DHEAD 64
#define DROPE 32

// ---------------------------------------------------------------------------
// Scratch (device globals; no allocation anywhere)
// ---------------------------------------------------------------------------
__device__ float g_proj[(size_t)BATCH * CDIM * TDIM];      // q projection [B,C,T]
__device__ float g_kv  [(size_t)BATCH * 2 * CDIM * TDIM];  // kv projection [B,2C,T]
__device__ float g_q   [(size_t)BATCH * CDIM * TDIM];      // Q [B,H,T,DH]
__device__ float g_k   [(size_t)BATCH * CDIM * TDIM];      // K [B,H,T,DH]
__device__ float g_v   [(size_t)BATCH * CDIM * TDIM];      // V [B,H,T,DH]
__device__ float g_attn[(size_t)BATCH * CDIM * TDIM];      // attn output [B,C,T]

// ---------------------------------------------------------------------------
// Tiled SGEMM (single-buffered, conservative — component under bisect test):
// C[b] = A @ X[b] + bias ;  A: [M,K] row-major (weights, unbatched)
// X: [K,N] row-major per batch. 256 threads, BM=BN=128, BK=8, 8x8/thread.
// ---------------------------------------------------------------------------
#define BM 128
#define BN 128
#define BK 8
#define TM 8
#define TN 8

__global__ __launch_bounds__(256)
void sgemm_bias(const float* __restrict__ A, const float* __restrict__ X,
                const float* __restrict__ bias, float* __restrict__ C,
                int M, int K, long xBatchStride, long cBatchStride)
{
    const int N = TDIM;
    int b  = blockIdx.z;
    int br = blockIdx.y;
    int bc = blockIdx.x;
    const float* Xp = X + (long)b * xBatchStride;
    float*       Cp = C + (long)b * cBatchStride;

    __shared__ float As[BK][BM];
    __shared__ float Bs[BK][BN];

    int tid  = threadIdx.x;
    int arow = tid >> 1;            // 0..127 (M row within tile)
    int acol = (tid & 1) << 2;      // 0 or 4 (k offset)
    int brow = tid >> 5;            // 0..7   (k row)
    int bcol = (tid & 31) << 2;     // 0..124 (N col)

    int tx = tid & 15;              // col group
    int ty = tid >> 4;              // row group

    float acc[TM][TN];
    #pragma unroll
    for (int i = 0; i < TM; i++)
        #pragma unroll
        for (int j = 0; j < TN; j++) acc[i][j] = 0.f;

    const float* Aofs = A  + (long)(br * BM + arow) * K + acol;
    const float* Bofs = Xp + (long)brow * N + bc * BN + bcol;

    for (int k0 = 0; k0 < K; k0 += BK) {
        float4 av = *(const float4*)(Aofs + k0);
        float4 bv = *(const float4*)(Bofs + (long)k0 * N);
        As[acol + 0][arow] = av.x;
        As[acol + 1][arow] = av.y;
        As[acol + 2][arow] = av.z;
        As[acol + 3][arow] = av.w;
        *(float4*)&Bs[brow][bcol] = bv;
        __syncthreads();

        #pragma unroll
        for (int kk = 0; kk < BK; kk++) {
            float ra[TM], rb[TN];
            #pragma unroll
            for (int i = 0; i < TM; i++) ra[i] = As[kk][ty * TM + i];
            #pragma unroll
            for (int j = 0; j < TN; j++) rb[j] = Bs[kk][tx * TN + j];
            #pragma unroll
            for (int i = 0; i < TM; i++)
                #pragma unroll
                for (int j = 0; j < TN; j++) acc[i][j] += ra[i] * rb[j];
        }
        __syncthreads();
    }

    #pragma unroll
    for (int i = 0; i < TM; i++) {
        int row = br * BM + ty * TM + i;
        float bvv = bias[row];
        float* crow = Cp + (long)row * N + bc * BN + tx * TN;
        float4 o0, o1;
        o0.x = acc[i][0] + bvv; o0.y = acc[i][1] + bvv;
        o0.z = acc[i][2] + bvv; o0.w = acc[i][3] + bvv;
        o1.x = acc[i][4] + bvv; o1.y = acc[i][5] + bvv;
        o1.z = acc[i][6] + bvv; o1.w = acc[i][7] + bvv;
        *(float4*)(crow)     = o0;
        *(float4*)(crow + 4) = o1;
    }
}

// ---------------------------------------------------------------------------
// Build Q, K, V in [B,H,T,DH] (verified correct in R14 pass — unchanged).
// ---------------------------------------------------------------------------
__global__ __launch_bounds__(256)
void build_qkv(const float* __restrict__ qproj,   // [B][C][T]
               const float* __restrict__ kvproj,  // [B][2C][T]
               float* __restrict__ Qd, float* __restrict__ Kd,
               float* __restrict__ Vd)
{
    long gid = (long)blockIdx.x * blockDim.x + threadIdx.x;  // < B*H*DH*T = 4M
    int  t  = (int)(gid & (TDIM - 1));
    long r  = gid >> 10;            // b*H*DH + h*DH + d
    int  d  = (int)(r & (DHEAD - 1));
    long bh = r >> 6;               // b*H + h
    int  h  = (int)(bh & (HEADS - 1));
    int  b  = (int)(bh >> 4);

    float qv = qproj [((long)b * CDIM     + h * DHEAD + d) * TDIM + t];
    float kv = kvproj[((long)b * 2 * CDIM + h * DHEAD + d) * TDIM + t];
    float vv = kvproj[((long)b * 2 * CDIM + CDIM + h * DHEAD + d) * TDIM + t];

    if (d < DROPE) {
        int   j     = (d < 16) ? d : d - 16;
        float theta = powf(10000.f, -(float)(2 * j) / 32.f);
        float ang   = theta * (float)t;
        float cs    = cosf(ang);
        float sn    = sinf(ang);
        int   pd    = (d < 16) ? d + 16 : d - 16;
        float sgn   = (d < 16) ? -1.f : 1.f;
        float qp = qproj [((long)b * CDIM     + h * DHEAD + pd) * TDIM + t];
        float kp = kvproj[((long)b * 2 * CDIM + h * DHEAD + pd) * TDIM + t];
        qv = qv * cs + sgn * qp * sn;
        kv = kv * cs + sgn * kp * sn;
    }

    long dst = (((long)(b * HEADS + h) * TDIM) + t) * DHEAD + d;
    Qd[dst] = qv * 0.125f;   // fold score scale into Q
    Kd[dst] = kv;
    Vd[dst] = vv;
}

// ---------------------------------------------------------------------------
// Naive attention (verified correct): one warp per (b, h, q) row.
// Pass 1: row max.  Pass 2 (merged old 2+3): accumulate l and weighted V in
// the same k-order — bit-identical arithmetic to the 3-pass version.
// ---------------------------------------------------------------------------
__global__ __launch_bounds__(128)
void attn_naive(const float* __restrict__ Qd, const float* __restrict__ Kd,
                const float* __restrict__ Vd, float* __restrict__ Od)
{
    int warp = threadIdx.x >> 5;        // 0..3
    int lane = threadIdx.x & 31;
    int qrow = blockIdx.x * 4 + warp;   // 0..T-1
    int h = blockIdx.y;
    int b = blockIdx.z;

    const float* Qr  = Qd + (((long)(b * HEADS + h) * TDIM) + qrow) * DHEAD;
    const float* Kbh = Kd + ((long)(b * HEADS + h) * TDIM) * DHEAD;
    const float* Vbh = Vd + ((long)(b * HEADS + h) * TDIM) * DHEAD;

    float2 qv = *(const float2*)(Qr + lane * 2);

    // pass 1: row max
    float m = -INFINITY;
    for (int k = 0; k < TDIM; k++) {
        float2 kv2 = *(const float2*)(Kbh + (long)k * DHEAD + lane * 2);
        float p = qv.x * kv2.x + qv.y * kv2.y;
        #pragma unroll
        for (int o = 16; o >= 1; o >>= 1) p += __shfl_xor_sync(0xffffffffu, p, o);
        m = fmaxf(m, p);
    }

    // pass 2: denominator + weighted V accumulation (same k-order as before)
    float l = 0.f, a0 = 0.f, a1 = 0.f;
    for (int k = 0; k < TDIM; k++) {
        float2 kv2 = *(const float2*)(Kbh + (long)k * DHEAD + lane * 2);
        float p = qv.x * kv2.x + qv.y * kv2.y;
        #pragma unroll
        for (int o = 16; o >= 1; o >>= 1) p += __shfl_xor_sync(0xffffffffu, p, o);
        float w = expf(p - m);
        l += w;
        float2 vv = *(const float2*)(Vbh + (long)k * DHEAD + lane * 2);
        a0 = fmaf(w, vv.x, a0);
        a1 = fmaf(w, vv.y, a1);
    }

    float inv = 1.f / l;
    long base = ((long)b * CDIM + h * DHEAD) * TDIM + qrow;
    Od[base + (long)(lane * 2    ) * TDIM] = a0 * inv;
    Od[base + (long)(lane * 2 + 1) * TDIM] = a1 * inv;
}

// ---------------------------------------------------------------------------
// Host launcher
// ---------------------------------------------------------------------------
extern "C" void kernel_launch(void* const* d_in, const int* in_sizes, int n_in,
                              void* d_out, int out_size)
{
    const float* x    = (const float*)d_in[0];
    const float* c    = (const float*)d_in[1];
    const float* q_w  = (const float*)d_in[2];
    const float* q_b  = (const float*)d_in[3];
    const float* kv_w = (const float*)d_in[4];
    const float* kv_b = (const float*)d_in[5];
    const float* o_w  = (const float*)d_in[6];
    const float* o_b  = (const float*)d_in[7];
    float* out = (float*)d_out;

    float *proj, *kv, *qr, *kr, *vr, *attnOut;
    cudaGetSymbolAddress((void**)&proj,    g_proj);
    cudaGetSymbolAddress((void**)&kv,      g_kv);
    cudaGetSymbolAddress((void**)&qr,      g_q);
    cudaGetSymbolAddress((void**)&kr,      g_k);
    cudaGetSymbolAddress((void**)&vr,      g_v);
    cudaGetSymbolAddress((void**)&attnOut, g_attn);

    const long CT  = (long)CDIM * TDIM;     // 1M
    const long C2T = 2 * CT;                // 2M

    // q = q_w @ x + q_b      -> proj [B, C, T]   (tiled GEMM under test)
    sgemm_bias<<<dim3(TDIM / BN, CDIM / BM, BATCH), 256>>>(
        q_w, x, q_b, proj, CDIM, CDIM, CT, CT);

    // kv = kv_w @ c + kv_b   -> kv [B, 2C, T]
    sgemm_bias<<<dim3(TDIM / BN, 2 * CDIM / BM, BATCH), 256>>>(
        kv_w, c, kv_b, kv, 2 * CDIM, CDIM, CT, C2T);

    // Q/K/V build + RoPE      -> [B, H, T, DH]  (verified)
    {
        long total = (long)BATCH * HEADS * DHEAD * TDIM;   // 4M
        build_qkv<<<(unsigned)(total / 256), 256>>>(proj, kv, qr, kr, vr);
    }

    // attention               -> attnOut [B, C, T]  (verified, 2-pass)
    attn_naive<<<dim3(TDIM / 4, HEADS, BATCH), 128>>>(qr, kr, vr, attnOut);

    // out = o_w @ attn + o_b
    sgemm_bias<<<dim3(TDIM / BN, CDIM / BM, BATCH), 256>>>(
        o_w, attnOut, o_b, out, CDIM, CDIM, CT, CT);
}